// round 11
// baseline (speedup 1.0000x reference)
#include <cuda_runtime.h>

#define Bsz     32
#define Anch    3
#define Hd      160
#define Wd      160
#define NT      512
#define NCLS    3
#define PLANE   (Hd*Wd)                 // 25600
#define CONF_ELEMS (Bsz*Anch*PLANE)     // 2,457,600
#define PLANE_V4 (PLANE/4)              // 6400

#define NBLOCK  150
#define NTHREAD 256
#define NTH     (NBLOCK*NTHREAD)        // 38400 = 6 * PLANE_V4
#define NWARPS  (NTHREAD/32)            // 8
#define STRIDE4 307200                  // 6 planes * 51200 float4 per step

// per-block partials: [block][0..4] = conf_ss, conf_corr, box, cls, n
__device__ float g_partial[NBLOCK][5];
__device__ unsigned int g_flag[NBLOCK];   // zero-init; reset by block 0 each run

__device__ __forceinline__ float tanh_fast(float x) {
    float y;
    asm("tanh.approx.f32 %0, %1;" : "=f"(y) : "f"(x));
    return y;
}
// sigmoid(x) = 0.5 + 0.5*tanh(0.5x) : one MUFU
__device__ __forceinline__ float sigm(float x) {
    return fmaf(0.5f, tanh_fast(0.5f * x), 0.5f);
}

#define LDG4(dst, ptr)                                                        \
    asm volatile("ld.global.nc.v4.f32 {%0,%1,%2,%3}, [%4];"                   \
                 : "=f"(dst.x), "=f"(dst.y), "=f"(dst.z), "=f"(dst.w)         \
                 : "l"(ptr))

__device__ __forceinline__ void st_release(unsigned int* p, unsigned int v) {
    asm volatile("st.release.gpu.global.u32 [%0], %1;" :: "l"(p), "r"(v) : "memory");
}
__device__ __forceinline__ unsigned int ld_acquire(const unsigned int* p) {
    unsigned int v;
    asm volatile("ld.acquire.gpu.global.u32 %0, [%1];" : "=r"(v) : "l"(p) : "memory");
    return v;
}

// accumulate (1+tanh(x/2))^2 ; caller scales by 0.25 once
__device__ __forceinline__ void usq4(float4 v, float& acc) {
    float u0 = 1.0f + tanh_fast(0.5f * v.x);
    float u1 = 1.0f + tanh_fast(0.5f * v.y);
    float u2 = 1.0f + tanh_fast(0.5f * v.z);
    float u3 = 1.0f + tanh_fast(0.5f * v.w);
    acc = fmaf(u0, u0, acc);
    acc = fmaf(u1, u1, acc);
    acc = fmaf(u2, u2, acc);
    acc = fmaf(u3, u3, acc);
}

__global__ void __launch_bounds__(NTHREAD)
detection_loss_kernel(const float* __restrict__ pred,
                      const float* __restrict__ targets,
                      float* __restrict__ out)
{
    const int tid = blockIdx.x * NTHREAD + threadIdx.x;

    float acc[5] = {0.f, 0.f, 0.f, 0.f, 0.f};
    // [0]=conf_sumsq [1]=conf_corr [2]=box [3]=cls [4]=n

    // ---- dense pass: 16 constant-stride float4 loads, exact cover ----
    {
        const int q = tid / PLANE_V4;            // 0..5  (one div total)
        const int r = tid - q * PLANE_V4;        // 0..6399
        const float4* p = reinterpret_cast<const float4*>(pred)
                        + (size_t)(51200 * q + 25600 + r);

        float4 x0,x1,x2,x3,x4,x5,x6,x7,x8,x9,xa,xb,xc,xd,xe,xf;
        LDG4(x0, p);               LDG4(x1, p + 1*STRIDE4);
        LDG4(x2, p + 2*STRIDE4);   LDG4(x3, p + 3*STRIDE4);
        LDG4(x4, p + 4*STRIDE4);   LDG4(x5, p + 5*STRIDE4);
        LDG4(x6, p + 6*STRIDE4);   LDG4(x7, p + 7*STRIDE4);
        LDG4(x8, p + 8*STRIDE4);   LDG4(x9, p + 9*STRIDE4);
        LDG4(xa, p + 10*STRIDE4);  LDG4(xb, p + 11*STRIDE4);
        LDG4(xc, p + 12*STRIDE4);  LDG4(xd, p + 13*STRIDE4);
        LDG4(xe, p + 14*STRIDE4);  LDG4(xf, p + 15*STRIDE4);

        float s = 0.f;
        usq4(x0, s); usq4(x1, s); usq4(x2, s); usq4(x3, s);
        usq4(x4, s); usq4(x5, s); usq4(x6, s); usq4(x7, s);
        usq4(x8, s); usq4(x9, s); usq4(xa, s); usq4(xb, s);
        usq4(xc, s); usq4(xd, s); usq4(xe, s); usq4(xf, s);
        acc[0] = 0.25f * s;
    }

    // ---- sparse pass: one item per (target, anchor); 1536 items ----
    if (tid < NT * Anch) {
        int t = tid / Anch;
        int a = tid - t * Anch;
        float tb = targets[t*6 + 0];
        float tc = targets[t*6 + 1];
        float tx = targets[t*6 + 2];
        float ty = targets[t*6 + 3];
        float tw = targets[t*6 + 4];
        float th = targets[t*6 + 5];
        int b  = (int)tb;
        int c  = (int)tc;
        int gx = (int)(tx * (float)Wd);
        int gy = (int)(ty * (float)Hd);
        if (gx >= 0 && gx < Wd && gy >= 0 && gy < Hd && b >= 0 && b < Bsz) {
            const float* base = pred + (size_t)(b * 24 + a * 8) * PLANE
                                     + (size_t)gy * Wd + gx;
            float p0 = base[0*PLANE];
            float p1 = base[1*PLANE];
            float p2 = base[2*PLANE];
            float p3 = base[3*PLANE];
            float p4v = base[4*PLANE];
            float p5 = base[5*PLANE];
            float p6 = base[6*PLANE];
            float p7 = base[7*PLANE];

            float bx = sigm(p0) - tx;
            float by = sigm(p1) - ty;
            float bw = __expf(p2) - tw;
            float bh = __expf(p3) - th;
            acc[2] = bx*bx + by*by + bw*bw + bh*bh;

            acc[1] = 1.0f - 2.0f * sigm(p4v);        // (s-1)^2 - s^2

            float t0 = (c == 0) ? 1.0f : 0.0f;
            float t1 = (c == 1) ? 1.0f : 0.0f;
            float t2 = (c == 2) ? 1.0f : 0.0f;
            float d0 = sigm(p5) - t0;
            float d1 = sigm(p6) - t1;
            float d2 = sigm(p7) - t2;
            acc[3] = d0*d0 + d1*d1 + d2*d2;

            acc[4] = 1.0f;
        }
    }

    // ---- block reduction: float warp shuffles, then shared ----
    #pragma unroll
    for (int o = 16; o > 0; o >>= 1)
        #pragma unroll
        for (int i = 0; i < 5; i++)
            acc[i] += __shfl_down_sync(0xFFFFFFFFu, acc[i], o);

    __shared__ float sh[NWARPS][5];
    int wid = threadIdx.x >> 5;
    int lid = threadIdx.x & 31;
    if (lid == 0)
        #pragma unroll
        for (int i = 0; i < 5; i++) sh[wid][i] = acc[i];
    __syncthreads();

    if (blockIdx.x != 0) {
        // producer: publish partials, then release-store my flag. No fence,
        // no contended atomic — release orders the 5 st.cg before the flag.
        if (threadIdx.x == 0) {
            float tot[5] = {0.f, 0.f, 0.f, 0.f, 0.f};
            #pragma unroll
            for (int w = 0; w < NWARPS; w++)
                #pragma unroll
                for (int i = 0; i < 5; i++) tot[i] += sh[w][i];
            #pragma unroll
            for (int i = 0; i < 5; i++)
                __stcg(&g_partial[blockIdx.x][i], tot[i]);
            st_release(&g_flag[blockIdx.x], 1u);
        }
        return;
    }

    // ---- block 0, warp 0: spin on flags, gather, finalize ----
    if (wid == 0) {
        // poll flags 1..149: lane l owns flags l+1, l+33, l+65, l+97, l+129
        bool done = false;
        while (!done) {
            unsigned int ok = 1u;
            #pragma unroll
            for (int j = 0; j < 5; j++) {
                int i = 1 + lid + j * 32;
                if (i < NBLOCK) ok &= ld_acquire(&g_flag[i]);
            }
            done = __all_sync(0xFFFFFFFFu, ok != 0u);
        }
        // all flags seen with acquire -> all partials visible
        float v[5] = {0.f, 0.f, 0.f, 0.f, 0.f};
        #pragma unroll
        for (int j = 0; j < 5; j++) {
            int i = 1 + lid + j * 32;
            if (i < NBLOCK) {
                #pragma unroll
                for (int k = 0; k < 5; k++)
                    v[k] += __ldcg(&g_partial[i][k]);
            }
        }
        #pragma unroll
        for (int o = 16; o > 0; o >>= 1)
            #pragma unroll
            for (int k = 0; k < 5; k++)
                v[k] += __shfl_down_sync(0xFFFFFFFFu, v[k], o);

        if (lid == 0) {
            double tot[5];
            #pragma unroll
            for (int k = 0; k < 5; k++) tot[k] = (double)v[k];
            #pragma unroll
            for (int w = 0; w < NWARPS; w++)          // block 0's own partials
                #pragma unroll
                for (int k = 0; k < 5; k++) tot[k] += (double)sh[w][k];
            double loss_conf = (tot[0] + tot[1]) / (double)CONF_ELEMS;
            double loss_box  = tot[2] / (tot[4] * 4.0);
            double loss_cls  = tot[3] / (tot[4] * (double)NCLS);
            out[0] = (float)(5.0 * loss_box + loss_conf + loss_cls);
        }
        // reset flags for next graph replay (kernel boundary orders this)
        #pragma unroll
        for (int j = 0; j < 5; j++) {
            int i = 1 + lid + j * 32;
            if (i < NBLOCK) g_flag[i] = 0u;
        }
    }
}

extern "C" void kernel_launch(void* const* d_in, const int* in_sizes, int n_in,
                              void* d_out, int out_size)
{
    const float* pred    = (const float*)d_in[0];
    const float* targets = (const float*)d_in[1];
    float* out = (float*)d_out;
    detection_loss_kernel<<<NBLOCK, NTHREAD>>>(pred, targets, out);
}

// round 12
// speedup vs baseline: 1.1265x; 1.1265x over previous
#include <cuda_runtime.h>

#define Bsz     32
#define Anch    3
#define Hd      160
#define Wd      160
#define NT      512
#define NCLS    3
#define PLANE   (Hd*Wd)                 // 25600
#define CONF_ELEMS (Bsz*Anch*PLANE)     // 2,457,600
#define PLANE_V4 (PLANE/4)              // 6400

#define NBLOCK  120
#define NTHREAD 320
#define NTH     (NBLOCK*NTHREAD)        // 38400 = 6 * PLANE_V4 (exact cover)
#define NWARPS  (NTHREAD/32)            // 10
#define STRIDE4 307200                  // 6 planes * 51200 float4 per step

// per-block partials: [block][0..4] = conf_ss, conf_corr, box, cls, n
__device__ float g_partial[NBLOCK][5];

__device__ __forceinline__ float tanh_fast(float x) {
    float y;
    asm("tanh.approx.f32 %0, %1;" : "=f"(y) : "f"(x));
    return y;
}
// sigmoid(x) = 0.5 + 0.5*tanh(0.5x) : one MUFU
__device__ __forceinline__ float sigm(float x) {
    return fmaf(0.5f, tanh_fast(0.5f * x), 0.5f);
}

#define LDG4(dst, ptr)                                                        \
    asm volatile("ld.global.nc.v4.f32 {%0,%1,%2,%3}, [%4];"                   \
                 : "=f"(dst.x), "=f"(dst.y), "=f"(dst.z), "=f"(dst.w)         \
                 : "l"(ptr))

// accumulate (1+tanh(x/2))^2 ; caller scales by 0.25 once
__device__ __forceinline__ void usq4(float4 v, float& acc) {
    float u0 = 1.0f + tanh_fast(0.5f * v.x);
    float u1 = 1.0f + tanh_fast(0.5f * v.y);
    float u2 = 1.0f + tanh_fast(0.5f * v.z);
    float u3 = 1.0f + tanh_fast(0.5f * v.w);
    acc = fmaf(u0, u0, acc);
    acc = fmaf(u1, u1, acc);
    acc = fmaf(u2, u2, acc);
    acc = fmaf(u3, u3, acc);
}

__global__ void __launch_bounds__(NTHREAD)
detection_loss_main(const float* __restrict__ pred,
                    const float* __restrict__ targets)
{
    // Fire the PDL trigger immediately: lets the finalize kernel's launch
    // latency overlap this kernel's entire execution.
    cudaTriggerProgrammaticLaunchCompletion();

    const int tid = blockIdx.x * NTHREAD + threadIdx.x;

    float acc[5] = {0.f, 0.f, 0.f, 0.f, 0.f};
    // [0]=conf_sumsq [1]=conf_corr [2]=box [3]=cls [4]=n

    // ---- dense pass: 16 constant-stride float4 loads, exact cover ----
    {
        const int q = tid / PLANE_V4;            // 0..5  (one div total)
        const int r = tid - q * PLANE_V4;        // 0..6399
        const float4* p = reinterpret_cast<const float4*>(pred)
                        + (size_t)(51200 * q + 25600 + r);

        float4 x0,x1,x2,x3,x4,x5,x6,x7,x8,x9,xa,xb,xc,xd,xe,xf;
        LDG4(x0, p);               LDG4(x1, p + 1*STRIDE4);
        LDG4(x2, p + 2*STRIDE4);   LDG4(x3, p + 3*STRIDE4);
        LDG4(x4, p + 4*STRIDE4);   LDG4(x5, p + 5*STRIDE4);
        LDG4(x6, p + 6*STRIDE4);   LDG4(x7, p + 7*STRIDE4);
        LDG4(x8, p + 8*STRIDE4);   LDG4(x9, p + 9*STRIDE4);
        LDG4(xa, p + 10*STRIDE4);  LDG4(xb, p + 11*STRIDE4);
        LDG4(xc, p + 12*STRIDE4);  LDG4(xd, p + 13*STRIDE4);
        LDG4(xe, p + 14*STRIDE4);  LDG4(xf, p + 15*STRIDE4);

        float s = 0.f;
        usq4(x0, s); usq4(x1, s); usq4(x2, s); usq4(x3, s);
        usq4(x4, s); usq4(x5, s); usq4(x6, s); usq4(x7, s);
        usq4(x8, s); usq4(x9, s); usq4(xa, s); usq4(xb, s);
        usq4(xc, s); usq4(xd, s); usq4(xe, s); usq4(xf, s);
        acc[0] = 0.25f * s;
    }

    // ---- sparse pass: one item per (target, anchor); 1536 items ----
    if (tid < NT * Anch) {
        int t = tid / Anch;
        int a = tid - t * Anch;
        float tb = targets[t*6 + 0];
        float tc = targets[t*6 + 1];
        float tx = targets[t*6 + 2];
        float ty = targets[t*6 + 3];
        float tw = targets[t*6 + 4];
        float th = targets[t*6 + 5];
        int b  = (int)tb;
        int c  = (int)tc;
        int gx = (int)(tx * (float)Wd);
        int gy = (int)(ty * (float)Hd);
        if (gx >= 0 && gx < Wd && gy >= 0 && gy < Hd && b >= 0 && b < Bsz) {
            const float* base = pred + (size_t)(b * 24 + a * 8) * PLANE
                                     + (size_t)gy * Wd + gx;
            float p0 = base[0*PLANE];
            float p1 = base[1*PLANE];
            float p2 = base[2*PLANE];
            float p3 = base[3*PLANE];
            float p4v = base[4*PLANE];
            float p5 = base[5*PLANE];
            float p6 = base[6*PLANE];
            float p7 = base[7*PLANE];

            float bx = sigm(p0) - tx;
            float by = sigm(p1) - ty;
            float bw = __expf(p2) - tw;
            float bh = __expf(p3) - th;
            acc[2] = bx*bx + by*by + bw*bw + bh*bh;

            acc[1] = 1.0f - 2.0f * sigm(p4v);        // (s-1)^2 - s^2

            float t0 = (c == 0) ? 1.0f : 0.0f;
            float t1 = (c == 1) ? 1.0f : 0.0f;
            float t2 = (c == 2) ? 1.0f : 0.0f;
            float d0 = sigm(p5) - t0;
            float d1 = sigm(p6) - t1;
            float d2 = sigm(p7) - t2;
            acc[3] = d0*d0 + d1*d1 + d2*d2;

            acc[4] = 1.0f;
        }
    }

    // ---- block reduction: float warp shuffles, then shared ----
    #pragma unroll
    for (int o = 16; o > 0; o >>= 1)
        #pragma unroll
        for (int i = 0; i < 5; i++)
            acc[i] += __shfl_down_sync(0xFFFFFFFFu, acc[i], o);

    __shared__ float sh[NWARPS][5];
    int wid = threadIdx.x >> 5;
    int lid = threadIdx.x & 31;
    if (lid == 0)
        #pragma unroll
        for (int i = 0; i < 5; i++) sh[wid][i] = acc[i];
    __syncthreads();

    if (threadIdx.x == 0) {
        float tot[5] = {0.f, 0.f, 0.f, 0.f, 0.f};
        #pragma unroll
        for (int w = 0; w < NWARPS; w++)
            #pragma unroll
            for (int i = 0; i < 5; i++) tot[i] += sh[w][i];
        #pragma unroll
        for (int i = 0; i < 5; i++)
            __stcg(&g_partial[blockIdx.x][i], tot[i]);
    }
}

__global__ void __launch_bounds__(256)
detection_loss_finalize(float* __restrict__ out)
{
    // Wait for the main kernel to fully complete (memory visible) — this is
    // the correctness gate; the launch itself already overlapped main.
    cudaGridDependencySynchronize();

    int t = threadIdx.x;
    float v[5] = {0.f, 0.f, 0.f, 0.f, 0.f};
    if (t < NBLOCK) {
        #pragma unroll
        for (int k = 0; k < 5; k++) v[k] = __ldcg(&g_partial[t][k]);
    }
    #pragma unroll
    for (int o = 16; o > 0; o >>= 1)
        #pragma unroll
        for (int k = 0; k < 5; k++)
            v[k] += __shfl_down_sync(0xFFFFFFFFu, v[k], o);

    __shared__ float sh[8][5];
    int wid = t >> 5;
    if ((t & 31) == 0)
        #pragma unroll
        for (int k = 0; k < 5; k++) sh[wid][k] = v[k];
    __syncthreads();

    if (t == 0) {
        double tot[5] = {0, 0, 0, 0, 0};
        #pragma unroll
        for (int w = 0; w < 8; w++)
            #pragma unroll
            for (int k = 0; k < 5; k++) tot[k] += (double)sh[w][k];
        double loss_conf = (tot[0] + tot[1]) / (double)CONF_ELEMS;
        double loss_box  = tot[2] / (tot[4] * 4.0);
        double loss_cls  = tot[3] / (tot[4] * (double)NCLS);
        out[0] = (float)(5.0 * loss_box + loss_conf + loss_cls);
    }
}

extern "C" void kernel_launch(void* const* d_in, const int* in_sizes, int n_in,
                              void* d_out, int out_size)
{
    const float* pred    = (const float*)d_in[0];
    const float* targets = (const float*)d_in[1];
    float* out = (float*)d_out;

    detection_loss_main<<<NBLOCK, NTHREAD>>>(pred, targets);

    // Finalize with Programmatic Dependent Launch: its launch overlaps the
    // main kernel; cudaGridDependencySynchronize() inside gates correctness.
    cudaLaunchConfig_t cfg = {};
    cfg.gridDim  = dim3(1, 1, 1);
    cfg.blockDim = dim3(256, 1, 1);
    cfg.dynamicSmemBytes = 0;
    cfg.stream = 0;
    cudaLaunchAttribute attr[1];
    attr[0].id = cudaLaunchAttributeProgrammaticStreamSerialization;
    attr[0].val.programmaticStreamSerializationAllowed = 1;
    cfg.attrs = attr;
    cfg.numAttrs = 1;
    cudaLaunchKernelEx(&cfg, detection_loss_finalize, out);
}

// round 14
// speedup vs baseline: 1.5131x; 1.3431x over previous
#include <cuda_runtime.h>

#define Bsz     32
#define Anch    3
#define Hd      160
#define Wd      160
#define NT      512
#define NCLS    3
#define PLANE   (Hd*Wd)                 // 25600
#define CONF_ELEMS (Bsz*Anch*PLANE)     // 2,457,600
#define PLANE_V4 (PLANE/4)              // 6400

#define NBLOCK  120
#define NBPAD   128                     // padded; cols 120..127 stay zero
#define NTHREAD 320
#define NTH     (NBLOCK*NTHREAD)        // 38400 = 6 * PLANE_V4 (exact cover)
#define NWARPS  (NTHREAD/32)            // 10
#define STRIDE4 307200                  // 6 planes * 51200 float4 per step

// SoA partials: [k][block], k: 0=conf_ss 1=conf_corr 2=box 3=cls 4=n
__device__ float g_partial[5][NBPAD];

__device__ __forceinline__ float tanh_fast(float x) {
    float y;
    asm("tanh.approx.f32 %0, %1;" : "=f"(y) : "f"(x));
    return y;
}
// sigmoid(x) = 0.5 + 0.5*tanh(0.5x) : one MUFU
__device__ __forceinline__ float sigm(float x) {
    return fmaf(0.5f, tanh_fast(0.5f * x), 0.5f);
}

#define LDG4(dst, ptr)                                                        \
    asm volatile("ld.global.nc.v4.f32 {%0,%1,%2,%3}, [%4];"                   \
                 : "=f"(dst.x), "=f"(dst.y), "=f"(dst.z), "=f"(dst.w)         \
                 : "l"(ptr))

// accumulate (1+tanh(x/2))^2 ; caller scales by 0.25 once
__device__ __forceinline__ void usq4(float4 v, float& acc) {
    float u0 = 1.0f + tanh_fast(0.5f * v.x);
    float u1 = 1.0f + tanh_fast(0.5f * v.y);
    float u2 = 1.0f + tanh_fast(0.5f * v.z);
    float u3 = 1.0f + tanh_fast(0.5f * v.w);
    acc = fmaf(u0, u0, acc);
    acc = fmaf(u1, u1, acc);
    acc = fmaf(u2, u2, acc);
    acc = fmaf(u3, u3, acc);
}

__global__ void __launch_bounds__(NTHREAD)
detection_loss_main(const float* __restrict__ pred,
                    const float* __restrict__ targets)
{
    cudaTriggerProgrammaticLaunchCompletion();

    const int tid = blockIdx.x * NTHREAD + threadIdx.x;

    float acc[5] = {0.f, 0.f, 0.f, 0.f, 0.f};

    // ---- dense pass: 16 constant-stride float4 loads, exact cover ----
    {
        const int q = tid / PLANE_V4;            // 0..5  (one div total)
        const int r = tid - q * PLANE_V4;        // 0..6399
        const float4* p = reinterpret_cast<const float4*>(pred)
                        + (size_t)(51200 * q + 25600 + r);

        float4 x0,x1,x2,x3,x4,x5,x6,x7,x8,x9,xa,xb,xc,xd,xe,xf;
        LDG4(x0, p);               LDG4(x1, p + 1*STRIDE4);
        LDG4(x2, p + 2*STRIDE4);   LDG4(x3, p + 3*STRIDE4);
        LDG4(x4, p + 4*STRIDE4);   LDG4(x5, p + 5*STRIDE4);
        LDG4(x6, p + 6*STRIDE4);   LDG4(x7, p + 7*STRIDE4);
        LDG4(x8, p + 8*STRIDE4);   LDG4(x9, p + 9*STRIDE4);
        LDG4(xa, p + 10*STRIDE4);  LDG4(xb, p + 11*STRIDE4);
        LDG4(xc, p + 12*STRIDE4);  LDG4(xd, p + 13*STRIDE4);
        LDG4(xe, p + 14*STRIDE4);  LDG4(xf, p + 15*STRIDE4);

        float s = 0.f;
        usq4(x0, s); usq4(x1, s); usq4(x2, s); usq4(x3, s);
        usq4(x4, s); usq4(x5, s); usq4(x6, s); usq4(x7, s);
        usq4(x8, s); usq4(x9, s); usq4(xa, s); usq4(xb, s);
        usq4(xc, s); usq4(xd, s); usq4(xe, s); usq4(xf, s);
        acc[0] = 0.25f * s;
    }

    // ---- sparse pass: one item per (target, anchor); 1536 items ----
    if (tid < NT * Anch) {
        int t = tid / Anch;
        int a = tid - t * Anch;
        float tb = targets[t*6 + 0];
        float tc = targets[t*6 + 1];
        float tx = targets[t*6 + 2];
        float ty = targets[t*6 + 3];
        float tw = targets[t*6 + 4];
        float th = targets[t*6 + 5];
        int b  = (int)tb;
        int c  = (int)tc;
        int gx = (int)(tx * (float)Wd);
        int gy = (int)(ty * (float)Hd);
        if (gx >= 0 && gx < Wd && gy >= 0 && gy < Hd && b >= 0 && b < Bsz) {
            const float* base = pred + (size_t)(b * 24 + a * 8) * PLANE
                                     + (size_t)gy * Wd + gx;
            float p0 = base[0*PLANE];
            float p1 = base[1*PLANE];
            float p2 = base[2*PLANE];
            float p3 = base[3*PLANE];
            float p4v = base[4*PLANE];
            float p5 = base[5*PLANE];
            float p6 = base[6*PLANE];
            float p7 = base[7*PLANE];

            float bx = sigm(p0) - tx;
            float by = sigm(p1) - ty;
            float bw = __expf(p2) - tw;
            float bh = __expf(p3) - th;
            acc[2] = bx*bx + by*by + bw*bw + bh*bh;

            acc[1] = 1.0f - 2.0f * sigm(p4v);        // (s-1)^2 - s^2

            float t0 = (c == 0) ? 1.0f : 0.0f;
            float t1 = (c == 1) ? 1.0f : 0.0f;
            float t2 = (c == 2) ? 1.0f : 0.0f;
            float d0 = sigm(p5) - t0;
            float d1 = sigm(p6) - t1;
            float d2 = sigm(p7) - t2;
            acc[3] = d0*d0 + d1*d1 + d2*d2;

            acc[4] = 1.0f;
        }
    }

    // ---- block reduction: float warp shuffles, then shared ----
    #pragma unroll
    for (int o = 16; o > 0; o >>= 1)
        #pragma unroll
        for (int i = 0; i < 5; i++)
            acc[i] += __shfl_down_sync(0xFFFFFFFFu, acc[i], o);

    __shared__ float sh[NWARPS][5];
    int wid = threadIdx.x >> 5;
    int lid = threadIdx.x & 31;
    if (lid == 0)
        #pragma unroll
        for (int i = 0; i < 5; i++) sh[wid][i] = acc[i];
    __syncthreads();

    if (threadIdx.x == 0) {
        float tot[5] = {0.f, 0.f, 0.f, 0.f, 0.f};
        #pragma unroll
        for (int w = 0; w < NWARPS; w++)
            #pragma unroll
            for (int i = 0; i < 5; i++) tot[i] += sh[w][i];
        #pragma unroll
        for (int i = 0; i < 5; i++)
            g_partial[i][blockIdx.x] = tot[i];
    }
}

// Single-warp finalize: one L2 round (25 independent LDG.128), shuffles,
// float math, one STG. No shared memory, no __syncthreads.
__global__ void __launch_bounds__(32)
detection_loss_finalize(float* __restrict__ out)
{
    cudaGridDependencySynchronize();

    const int lid = threadIdx.x;                 // 0..31
    // lane l sums columns [4l, 4l+4) of each row; cols 120..127 are zero pad
    float4 r0 = *reinterpret_cast<const float4*>(&g_partial[0][lid*4]);
    float4 r1 = *reinterpret_cast<const float4*>(&g_partial[1][lid*4]);
    float4 r2 = *reinterpret_cast<const float4*>(&g_partial[2][lid*4]);
    float4 r3 = *reinterpret_cast<const float4*>(&g_partial[3][lid*4]);
    float4 r4 = *reinterpret_cast<const float4*>(&g_partial[4][lid*4]);

    float v[5];
    v[0] = r0.x + r0.y + r0.z + r0.w;
    v[1] = r1.x + r1.y + r1.z + r1.w;
    v[2] = r2.x + r2.y + r2.z + r2.w;
    v[3] = r3.x + r3.y + r3.z + r3.w;
    v[4] = r4.x + r4.y + r4.z + r4.w;

    #pragma unroll
    for (int o = 16; o > 0; o >>= 1)
        #pragma unroll
        for (int k = 0; k < 5; k++)
            v[k] += __shfl_down_sync(0xFFFFFFFFu, v[k], o);

    if (lid == 0) {
        float inv_n = __fdividef(1.0f, v[4]);
        float loss_conf = (v[0] + v[1]) * (1.0f / (float)CONF_ELEMS);
        float loss_box  = v[2] * inv_n * 0.25f;
        float loss_cls  = v[3] * inv_n * (1.0f / (float)NCLS);
        out[0] = 5.0f * loss_box + loss_conf + loss_cls;
    }
}

extern "C" void kernel_launch(void* const* d_in, const int* in_sizes, int n_in,
                              void* d_out, int out_size)
{
    const float* pred    = (const float*)d_in[0];
    const float* targets = (const float*)d_in[1];
    float* out = (float*)d_out;

    detection_loss_main<<<NBLOCK, NTHREAD>>>(pred, targets);

    cudaLaunchConfig_t cfg = {};
    cfg.gridDim  = dim3(1, 1, 1);
    cfg.blockDim = dim3(32, 1, 1);
    cfg.dynamicSmemBytes = 0;
    cfg.stream = 0;
    cudaLaunchAttribute attr[1];
    attr[0].id = cudaLaunchAttributeProgrammaticStreamSerialization;
    attr[0].val.programmaticStreamSerializationAllowed = 1;
    cfg.attrs = attr;
    cfg.numAttrs = 1;
    cudaLaunchKernelEx(&cfg, detection_loss_finalize, out);
}